// round 4
// baseline (speedup 1.0000x reference)
#include <cuda_runtime.h>

#define NB 1323        // batch rows (gaussians)
#define NPP 1323       // points per row (441*3)
#define DMODEL 1024
#define TOTAL (NB * NPP)           // 1750329 profile elements
#define PTS_PER_BLOCK 1024
#define NBLOCKS ((TOTAL + PTS_PER_BLOCK - 1) / PTS_PER_BLOCK)   // 1710
#define LOG_2PI 1.8378770664093453f

__device__ __forceinline__ float softplus_f(float x) {
    return fmaxf(x, 0.0f) + log1pf(expf(-fabsf(x)));
}

struct RowParams {
    float m0, m1, m2, inv00, L10, inv11, L20, L21, inv22, cc;
};

__device__ __forceinline__ float eval_point(const RowParams& q, float x, float y, float z) {
    float d0 = x - q.m0;
    float d1 = y - q.m1;
    float d2 = z - q.m2;
    float y0 = d0 * q.inv00;
    float y1 = fmaf(-q.L10, y0, d1) * q.inv11;
    float y2 = (d2 - fmaf(q.L20, y0, q.L21 * y1)) * q.inv22;
    float M = fmaf(y0, y0, fmaf(y1, y1, y2 * y2));
    return __expf(fmaf(-0.5f, M, q.cc));
}

// Derive the distilled params for one row from its 9 raw linear outputs,
// write L to gmem if this block owns the row start.
__device__ __forceinline__ void derive_params(const float* s,
                                              const float* bm, const float* bs,
                                              RowParams* dst,
                                              float* outL, unsigned row,
                                              bool write_L) {
    float m0 = s[0] + bm[0];
    float m1 = s[1] + bm[1];
    float m2 = s[2] + bm[2];
    float L00 = softplus_f(s[3] + bs[0]);
    float L10 = s[4] + bs[1];
    float L11 = softplus_f(s[5] + bs[2]);
    float L20 = s[6] + bs[3];
    float L21 = s[7] + bs[4];
    float L22 = softplus_f(s[8] + bs[5]);

    dst->m0 = m0; dst->m1 = m1; dst->m2 = m2;
    dst->inv00 = __frcp_rn(L00);
    dst->L10 = L10;
    dst->inv11 = __frcp_rn(L11);
    dst->L20 = L20; dst->L21 = L21;
    dst->inv22 = __frcp_rn(L22);
    dst->cc = -1.5f * LOG_2PI - (logf(L00) + logf(L11) + logf(L22));

    if (write_L) {
        float* Lo = outL + (size_t)row * 9;
        Lo[0] = L00; Lo[1] = 0.0f; Lo[2] = 0.0f;
        Lo[3] = L10; Lo[4] = L11;  Lo[5] = 0.0f;
        Lo[6] = L20; Lo[7] = L21;  Lo[8] = L22;
    }
}

// Fused kernel: block b owns points [b*1024, b*1024+1024) which span at most
// two gaussian rows. Phase 1: compute both rows' 9 linear outputs via a
// block-wide dot product (thread tid handles float4 chunk tid of 256).
// Phase 2: 4 points per thread.
__global__ __launch_bounds__(256, 5) void fused_kernel(
        const float* __restrict__ rep,
        const float* __restrict__ dxyz,
        const float* __restrict__ Wm,
        const float* __restrict__ bm,
        const float* __restrict__ Ws,
        const float* __restrict__ bs,
        float* __restrict__ outProfile,
        float* __restrict__ outL) {
    unsigned b = blockIdx.x;
    unsigned tid = threadIdx.x;          // 0..255
    unsigned p0 = b * (unsigned)PTS_PER_BLOCK;
    unsigned npts = min((unsigned)PTS_PER_BLOCK, (unsigned)TOTAL - p0);

    unsigned rowA = p0 / (unsigned)NPP;
    unsigned rowB = min(rowA + 1u, (unsigned)NB - 1u);
    unsigned sB = rowB * (unsigned)NPP;  // start point of rowB

    // ---------------- Phase 1: dual-row 9-way dot product ----------------
    const float4* rA4 = reinterpret_cast<const float4*>(rep + (size_t)rowA * DMODEL);
    const float4* rB4 = reinterpret_cast<const float4*>(rep + (size_t)rowB * DMODEL);
    const float4* wm4 = reinterpret_cast<const float4*>(Wm);
    const float4* ws4 = reinterpret_cast<const float4*>(Ws);

    float accA[9], accB[9];
    {
        float4 ra = __ldg(&rA4[tid]);
        float4 rb = __ldg(&rB4[tid]);
#pragma unroll
        for (int c = 0; c < 3; c++) {
            float4 w = __ldg(&wm4[c * (DMODEL / 4) + tid]);
            accA[c] = fmaf(ra.x, w.x, fmaf(ra.y, w.y, fmaf(ra.z, w.z, ra.w * w.w)));
            accB[c] = fmaf(rb.x, w.x, fmaf(rb.y, w.y, fmaf(rb.z, w.z, rb.w * w.w)));
        }
#pragma unroll
        for (int c = 0; c < 6; c++) {
            float4 w = __ldg(&ws4[c * (DMODEL / 4) + tid]);
            accA[3 + c] = fmaf(ra.x, w.x, fmaf(ra.y, w.y, fmaf(ra.z, w.z, ra.w * w.w)));
            accB[3 + c] = fmaf(rb.x, w.x, fmaf(rb.y, w.y, fmaf(rb.z, w.z, rb.w * w.w)));
        }
    }

    // warp reduce 18 values
#pragma unroll
    for (int c = 0; c < 9; c++) {
#pragma unroll
        for (int off = 16; off > 0; off >>= 1) {
            accA[c] += __shfl_down_sync(0xffffffffu, accA[c], off);
            accB[c] += __shfl_down_sync(0xffffffffu, accB[c], off);
        }
    }

    __shared__ float red[8][18];
    __shared__ RowParams qsh[2];
    unsigned wid = tid >> 5, lane = tid & 31;
    if (lane == 0) {
#pragma unroll
        for (int c = 0; c < 9; c++) { red[wid][c] = accA[c]; red[wid][9 + c] = accB[c]; }
    }
    __syncthreads();

    // threads 0 and 32 (different warps) derive params for rowA / rowB
    if (tid == 0) {
        float s[9];
#pragma unroll
        for (int c = 0; c < 9; c++) {
            float v = 0.0f;
#pragma unroll
            for (int w = 0; w < 8; w++) v += red[w][c];
            s[c] = v;
        }
        // rowA start inside block iff p0 is exactly a row start
        bool writeA = (rowA * (unsigned)NPP == p0);
        derive_params(s, bm, bs, &qsh[0], outL, rowA, writeA);
    } else if (tid == 32) {
        float s[9];
#pragma unroll
        for (int c = 0; c < 9; c++) {
            float v = 0.0f;
#pragma unroll
            for (int w = 0; w < 8; w++) v += red[w][9 + c];
            s[c] = v;
        }
        // rowB start inside block iff p0 < sB < p0+npts (sB > p0 holds when rowB!=rowA)
        bool writeB = (rowB != rowA) && (sB < p0 + npts);
        derive_params(s, bm, bs, &qsh[1], outL, rowB, writeB);
    }
    __syncthreads();

    // ---------------- Phase 2: 4 points per thread ----------------
    RowParams qa = qsh[0];
    RowParams qb = qsh[1];

    unsigned p = p0 + tid * 4u;
    if (p >= (unsigned)TOTAL) return;

    if (p + 4u <= (unsigned)TOTAL) {
        unsigned g = p >> 2;                 // float4-group index
        const float4* d4 = reinterpret_cast<const float4*>(dxyz);
        float4 a = __ldg(&d4[3u * g]);
        float4 v = __ldg(&d4[3u * g + 1u]);
        float4 c = __ldg(&d4[3u * g + 2u]);

        float xs[4] = {a.x, a.w, v.z, c.y};
        float ys[4] = {a.y, v.x, v.w, c.z};
        float zs[4] = {a.z, v.y, c.x, c.w};

        float r[4];
#pragma unroll
        for (int u = 0; u < 4; u++) {
            const RowParams& q = (p + (unsigned)u >= sB && rowB != rowA) ? qb : qa;
            r[u] = eval_point(q, xs[u], ys[u], zs[u]);
        }
        reinterpret_cast<float4*>(outProfile)[g] = make_float4(r[0], r[1], r[2], r[3]);
    } else {
        // tail (TOTAL % 4 == 1)
        for (; p < (unsigned)TOTAL; p++) {
            const RowParams& q = (p >= sB && rowB != rowA) ? qb : qa;
            outProfile[p] = eval_point(q, dxyz[3u * p], dxyz[3u * p + 1u], dxyz[3u * p + 2u]);
        }
    }
}

extern "C" void kernel_launch(void* const* d_in, const int* in_sizes, int n_in,
                              void* d_out, int out_size) {
    const float* rep  = (const float*)d_in[0];   // (B, 1024)
    const float* dxyz = (const float*)d_in[1];   // (B, NPTS, 3)
    const float* Wm   = (const float*)d_in[2];   // (3, 1024)
    const float* bm   = (const float*)d_in[3];   // (3,)
    const float* Ws   = (const float*)d_in[4];   // (6, 1024)
    const float* bs   = (const float*)d_in[5];   // (6,)
    // d_in[6] = num_planes (unused; reshape is identity)

    float* out = (float*)d_out;
    float* outProfile = out;            // TOTAL floats
    float* outL = out + TOTAL;          // NB*9 floats

    fused_kernel<<<NBLOCKS, 256>>>(rep, dxyz, Wm, bm, Ws, bs, outProfile, outL);
}

// round 6
// speedup vs baseline: 1.4064x; 1.4064x over previous
#include <cuda_runtime.h>

#define NB 1323        // batch rows (gaussians)
#define NPP 1323       // points per row (441*3)
#define DMODEL 1024
#define TOTAL (NB * NPP)           // 1750329 profile elements
#define LOG_2PI 1.8378770664093453f

// 12 floats per row (padded to 48B for aligned float4 loads):
// [m0, m1, m2, inv00, L10, inv11, L20, L21, inv22, cc, pad, pad]
__device__ float g_params[NB * 12];

__device__ __forceinline__ float softplus_f(float x) {
    return fmaxf(x, 0.0f) + log1pf(expf(-fabsf(x)));
}

// One 128-thread block per row. Each thread covers 8 of the 1024 rep elements
// (2 float4 chunks), accumulates 9 dot-product partials, block-reduces.
__global__ __launch_bounds__(128) void param_kernel(
        const float* __restrict__ rep,
        const float* __restrict__ Wm,
        const float* __restrict__ bm,
        const float* __restrict__ Ws,
        const float* __restrict__ bs,
        float* __restrict__ outL) {
    int row = blockIdx.x;
    int tid = threadIdx.x;          // 0..127
    int wid = tid >> 5;
    int lane = tid & 31;

    const float4* r4  = reinterpret_cast<const float4*>(rep + (size_t)row * DMODEL);
    const float4* wm4 = reinterpret_cast<const float4*>(Wm);
    const float4* ws4 = reinterpret_cast<const float4*>(Ws);

    float acc[9];
#pragma unroll
    for (int c = 0; c < 9; c++) acc[c] = 0.0f;

#pragma unroll
    for (int half = 0; half < 2; half++) {
        int k = tid + half * 128;
        float4 r = __ldg(&r4[k]);
#pragma unroll
        for (int c = 0; c < 3; c++) {
            float4 w = __ldg(&wm4[c * (DMODEL / 4) + k]);
            acc[c] = fmaf(r.x, w.x, fmaf(r.y, w.y, fmaf(r.z, w.z, fmaf(r.w, w.w, acc[c]))));
        }
#pragma unroll
        for (int c = 0; c < 6; c++) {
            float4 w = __ldg(&ws4[c * (DMODEL / 4) + k]);
            acc[3 + c] = fmaf(r.x, w.x, fmaf(r.y, w.y, fmaf(r.z, w.z, fmaf(r.w, w.w, acc[3 + c]))));
        }
    }

#pragma unroll
    for (int c = 0; c < 9; c++) {
#pragma unroll
        for (int off = 16; off > 0; off >>= 1)
            acc[c] += __shfl_down_sync(0xffffffffu, acc[c], off);
    }

    __shared__ float red[4][9];
    if (lane == 0) {
#pragma unroll
        for (int c = 0; c < 9; c++) red[wid][c] = acc[c];
    }
    __syncthreads();

    if (tid == 0) {
        float s[9];
#pragma unroll
        for (int c = 0; c < 9; c++)
            s[c] = red[0][c] + red[1][c] + red[2][c] + red[3][c];

        float m0 = s[0] + bm[0];
        float m1 = s[1] + bm[1];
        float m2 = s[2] + bm[2];

        float L00 = softplus_f(s[3] + bs[0]);
        float L10 = s[4] + bs[1];
        float L11 = softplus_f(s[5] + bs[2]);
        float L20 = s[6] + bs[3];
        float L21 = s[7] + bs[4];
        float L22 = softplus_f(s[8] + bs[5]);

        float inv00 = __frcp_rn(L00);
        float inv11 = __frcp_rn(L11);
        float inv22 = __frcp_rn(L22);
        float cc = -1.5f * LOG_2PI - (logf(L00) + logf(L11) + logf(L22));

        float* p = g_params + row * 12;
        p[0] = m0;    p[1] = m1;    p[2] = m2;    p[3] = inv00;
        p[4] = L10;   p[5] = inv11; p[6] = L20;   p[7] = L21;
        p[8] = inv22; p[9] = cc;    p[10] = 0.0f; p[11] = 0.0f;

        // L output: (B,1,3,3): [L00,0,0, L10,L11,0, L20,L21,L22]
        float* Lo = outL + (size_t)row * 9;
        Lo[0] = L00; Lo[1] = 0.0f; Lo[2] = 0.0f;
        Lo[3] = L10; Lo[4] = L11;  Lo[5] = 0.0f;
        Lo[6] = L20; Lo[7] = L21;  Lo[8] = L22;
    }
}

struct RowParams {
    float m0, m1, m2, inv00, L10, inv11, L20, L21, inv22, cc;
};

__device__ __forceinline__ RowParams load_params(unsigned row) {
    const float4* pp = reinterpret_cast<const float4*>(g_params + row * 12);
    float4 q0 = __ldg(&pp[0]);
    float4 q1 = __ldg(&pp[1]);
    float4 q2 = __ldg(&pp[2]);
    RowParams r;
    r.m0 = q0.x; r.m1 = q0.y; r.m2 = q0.z; r.inv00 = q0.w;
    r.L10 = q1.x; r.inv11 = q1.y; r.L20 = q1.z; r.L21 = q1.w;
    r.inv22 = q2.x; r.cc = q2.y;
    return r;
}

__device__ __forceinline__ float eval_point(const RowParams& q, float x, float y, float z) {
    float d0 = x - q.m0;
    float d1 = y - q.m1;
    float d2 = z - q.m2;
    float y0 = d0 * q.inv00;
    float y1 = fmaf(-q.L10, y0, d1) * q.inv11;
    float y2 = (d2 - fmaf(q.L20, y0, q.L21 * y1)) * q.inv22;
    float M = fmaf(y0, y0, fmaf(y1, y1, y2 * y2));
    return __expf(fmaf(-0.5f, M, q.cc));
}

// Each thread handles 4 consecutive points: 3 aligned float4 loads, 1 float4 store.
__global__ __launch_bounds__(256) void prob_kernel(const float* __restrict__ dxyz,
                                                   float* __restrict__ out) {
    unsigned t = blockIdx.x * blockDim.x + threadIdx.x;
    unsigned p0 = t * 4u;
    if (p0 >= TOTAL) return;

    if (p0 + 4u <= TOTAL) {
        const float4* d4 = reinterpret_cast<const float4*>(dxyz);
        float4 a = __ldg(&d4[3u * t]);
        float4 b = __ldg(&d4[3u * t + 1u]);
        float4 c = __ldg(&d4[3u * t + 2u]);

        float xs[4] = {a.x, a.w, b.z, c.y};
        float ys[4] = {a.y, b.x, b.w, c.z};
        float zs[4] = {a.z, b.y, c.x, c.w};

        unsigned i0 = p0 / (unsigned)NPP;          // row of first point
        unsigned i3 = (p0 + 3u) / (unsigned)NPP;   // row of last point
        RowParams qa = load_params(i0);
        float r[4];
        if (i0 == i3) {
#pragma unroll
            for (int u = 0; u < 4; u++)
                r[u] = eval_point(qa, xs[u], ys[u], zs[u]);
        } else {
            unsigned sB = i3 * (unsigned)NPP;      // start point of next row
            RowParams qb = load_params(i3);
#pragma unroll
            for (int u = 0; u < 4; u++) {
                const RowParams& q = (p0 + (unsigned)u >= sB) ? qb : qa;
                r[u] = eval_point(q, xs[u], ys[u], zs[u]);
            }
        }
        reinterpret_cast<float4*>(out)[t] = make_float4(r[0], r[1], r[2], r[3]);
    } else {
        // tail (TOTAL % 4 == 1): scalar path
        for (unsigned p = p0; p < TOTAL; p++) {
            unsigned i = p / (unsigned)NPP;
            RowParams q = load_params(i);
            out[p] = eval_point(q, dxyz[3u * p], dxyz[3u * p + 1u], dxyz[3u * p + 2u]);
        }
    }
}

extern "C" void kernel_launch(void* const* d_in, const int* in_sizes, int n_in,
                              void* d_out, int out_size) {
    const float* rep  = (const float*)d_in[0];   // (B, 1024)
    const float* dxyz = (const float*)d_in[1];   // (B, NPTS, 3)
    const float* Wm   = (const float*)d_in[2];   // (3, 1024)
    const float* bm   = (const float*)d_in[3];   // (3,)
    const float* Ws   = (const float*)d_in[4];   // (6, 1024)
    const float* bs   = (const float*)d_in[5];   // (6,)
    // d_in[6] = num_planes (unused; reshape is identity)

    float* out = (float*)d_out;
    float* outProfile = out;            // TOTAL floats
    float* outL = out + TOTAL;          // NB*9 floats

    // Kernel 1: per-row params + L output. One block per row.
    param_kernel<<<NB, 128>>>(rep, Wm, bm, Ws, bs, outL);

    // Kernel 2: main probability map. 4 points per thread.
    {
        unsigned groups = (TOTAL + 3u) / 4u;       // 437583
        unsigned blocks = (groups + 255u) / 256u;  // 1710
        prob_kernel<<<blocks, 256>>>(dxyz, outProfile);
    }
}